// round 7
// baseline (speedup 1.0000x reference)
#include <cuda_runtime.h>

#define NANCH 8732
#define NPAD  8736
#define NCLS  599
#define MC    300
#define CAP   4096
#define ROWD  604

typedef unsigned int u32;
typedef unsigned long long u64;

// ------------------- static device scratch (no allocations) -------------------
__device__ u32   g_sbits[2u * NCLS * NPAD];      // [B, C, Npad] masked score bits
__device__ u32   g_clsmax[2 * NCLS];             // per-class max score bits
__device__ u64   g_tkey[2];                      // global cutoff key per image
__device__ u64   g_key[2 * CAP];                 // compacted kept keys
__device__ u32   g_aux[2 * CAP];                 // anchor ids parallel to g_key
__device__ u32   g_cnt[2];                       // per-image append counters

// ------------------------------- reset ---------------------------------------
__global__ void k_reset() {
    int t = blockIdx.x * blockDim.x + threadIdx.x;
    if (t < 2) g_cnt[t] = 0;
    if (t < 2 * NCLS) g_clsmax[t] = 0;
}

// ---- streaming transpose: 64 anchors x 64 classes per CTA, masked bits out ----
__global__ void __launch_bounds__(512) k_prep(const float* __restrict__ in) {
    __shared__ float t[64][65];
    int b  = blockIdx.z;
    int n0 = blockIdx.x * 64;
    int c0 = blockIdx.y * 64;
    int tid = threadIdx.x, lane = tid & 31, w = tid >> 5;   // 16 warps

    #pragma unroll
    for (int r = 0; r < 4; r++) {
        int row = w * 4 + r;
        int n = n0 + row;
        float v0 = 0.f, v1 = 0.f;
        if (n < NANCH) {
            const float* src = in + ((size_t)b * NANCH + n) * ROWD + 1 + c0;
            if (c0 + lane < NCLS)      v0 = __ldg(&src[lane]);
            if (c0 + 32 + lane < NCLS) v1 = __ldg(&src[32 + lane]);
        }
        t[row][lane]      = v0;
        t[row][lane + 32] = v1;
    }
    __syncthreads();

    #pragma unroll
    for (int s = 0; s < 4; s++) {
        int cl  = s * 16 + w;
        int cgl = c0 + cl;
        float v0 = t[lane][cl];          // stride 65: conflict-free
        float v1 = t[lane + 32][cl];
        if (cgl < NCLS) {
            u32* dst = g_sbits + ((size_t)b * NCLS + cgl) * NPAD + n0;
            if (n0 + lane < NANCH)
                dst[lane]      = (v0 > 0.01f) ? __float_as_uint(v0) : 0u;
            if (n0 + 32 + lane < NANCH)
                dst[lane + 32] = (v1 > 0.01f) ? __float_as_uint(v1) : 0u;
        }
        float mx = fmaxf(v0, v1);
        #pragma unroll
        for (int off = 16; off; off >>= 1)
            mx = fmaxf(mx, __shfl_xor_sync(0xffffffffu, mx, off));
        if (lane == 0 && cgl < NCLS)
            atomicMax(&g_clsmax[b * NCLS + cgl], __float_as_uint(mx));
    }
}

// ------------- per-image cutoff = 200th largest class-max key ----------------
__global__ void __launch_bounds__(1024, 1) k_thresh() {
    __shared__ u64 a[1024];
    int b = blockIdx.x, tid = threadIdx.x;
    u64 p = 0;
    if (tid < NCLS) {
        u32 mb = g_clsmax[b * NCLS + tid];
        if (__uint_as_float(mb) > 0.01f)
            p = ((u64)mb << 32) | (u32)(~(u32)(tid * MC));
    }
    // hybrid bitonic 1024 desc
    #pragma unroll
    for (int k = 2; k <= 32; k <<= 1)
        #pragma unroll
        for (int j = k >> 1; j; j >>= 1) {
            u64 q = __shfl_xor_sync(0xffffffffu, p, j);
            bool keep_max = ((tid & k) == 0) == ((tid & j) == 0);
            bool sw = keep_max ? (q > p) : (q < p);
            if (sw) p = q;
        }
    a[tid] = p;
    __syncthreads();
    for (int k = 64; k <= 1024; k <<= 1) {
        for (int j = k >> 1; j >= 32; j >>= 1) {
            int i = tid, x = i ^ j;
            if (x > i) {
                u64 u1 = a[i], u2 = a[x];
                bool sw = ((i & k) == 0) ? (u1 < u2) : (u1 > u2);
                if (sw) { a[i] = u2; a[x] = u1; }
            }
            __syncthreads();
        }
        p = a[tid];
        #pragma unroll
        for (int j = 16; j; j >>= 1) {
            u64 q = __shfl_xor_sync(0xffffffffu, p, j);
            bool keep_max = ((tid & k) == 0) == ((tid & j) == 0);
            bool sw = keep_max ? (q > p) : (q < p);
            if (sw) p = q;
        }
        a[tid] = p;
        __syncthreads();
    }
    if (tid == 0) g_tkey[b] = a[199];
}

// -------- exact IoU>0.45 predicate with guarded div-free fast path -----------
__device__ __forceinline__ bool iou_gt(float y0, float x0, float y1, float x1, float a,
                                       float4 bj, float aj) {
    float ih = fmaxf(__fsub_rn(fminf(y1, bj.z), fmaxf(y0, bj.x)), 0.f);
    float iw = fmaxf(__fsub_rn(fminf(x1, bj.w), fmaxf(x0, bj.y)), 0.f);
    float inter = __fmul_rn(ih, iw);
    float uni   = __fsub_rn(__fadd_rn(a, aj), inter);
    if (!(uni > 0.f)) return false;
    float t = __fmul_rn(uni, 0.45f);
    if (inter > __fmul_rn(t, 1.000002f)) return true;
    if (inter < __fmul_rn(t, 0.999998f)) return false;
    return __fdiv_rn(inter, uni) > 0.45f;
}

// --------------- per-(b,c): top-300 select, matrix NMS, filtered append -------
__global__ void __launch_bounds__(512, 4) k_perclass(const float* __restrict__ in) {
    __shared__ __align__(16) char buf[9216 * 4];   // score bits, later NMS state
    __shared__ u32 hist[256], suf[256], wtot[8];
    __shared__ u64 cand[512];
    __shared__ u32 keepw[10];
    __shared__ u32 s_cnt, s_cut, s_ge, s_above;
    __shared__ u64 s_tkey;

    int c = blockIdx.x, b = blockIdx.y;
    int tid = threadIdx.x, lane = tid & 31, wid = tid >> 5;

    u32* ssc = (u32*)buf;
    const u32* sb = &g_sbits[((size_t)b * NCLS + c) * NPAD];

    if (tid < 256) hist[tid] = 0;
    if (tid == 0) { s_cnt = 0; s_tkey = g_tkey[b]; }
    __syncthreads();

    // ---- fused stage + radix pass-0 histogram ----
    #pragma unroll
    for (int e = 0; e < 18; e++) {
        int i = e * 512 + tid;
        u32 v = (i < NANCH) ? __ldg(&sb[i]) : 0u;
        ssc[i] = v;
        int bin = v >> 24;
        u32 grp = __match_any_sync(0xffffffffu, bin);
        if (lane == (u32)(__ffs(grp) - 1))
            atomicAdd(&hist[bin], __popc(grp));
    }
    __syncthreads();

    // ---- radix select, early exit when superset fits in 512 ----
    u32 prefix = 0, remain = MC, thresh = 0;
    for (int pass = 0; pass < 4; pass++) {
        int shift = 24 - 8 * pass;
        if (pass > 0) {
            if (tid < 256) hist[tid] = 0;
            __syncthreads();
            #pragma unroll
            for (int e = 0; e < 18; e++) {
                u32 u = ssc[e * 512 + tid];
                bool part = (u >> (shift + 8)) == prefix;
                int bin = (u >> shift) & 0xFF;
                int key = part ? bin : 999;
                u32 grp = __match_any_sync(0xffffffffu, key);
                if (part && lane == (u32)(__ffs(grp) - 1))
                    atomicAdd(&hist[bin], __popc(grp));
            }
            __syncthreads();
        }
        if (tid < 256) {
            u32 v = hist[tid];
            #pragma unroll
            for (int off = 1; off < 32; off <<= 1) {
                u32 o = __shfl_down_sync(0xffffffffu, v, off);
                if (lane + off < 32) v += o;
            }
            if (lane == 0) wtot[wid] = v;
            suf[tid] = v;
        }
        __syncthreads();
        if (tid < 256) {
            u32 add = 0;
            #pragma unroll
            for (int w2 = 0; w2 < 8; w2++)
                if (w2 > wid) add += wtot[w2];
            suf[tid] += add;
        }
        if (tid == 0) { s_cut = 0; s_ge = 0; s_above = 0; }
        __syncthreads();
        if (tid == 0 && suf[0] < remain) s_ge = suf[0];   // shortfall default
        if (tid < 256) {
            u32 ge = suf[tid];
            u32 ab = (tid == 255) ? 0u : suf[tid + 1];
            if (ge >= remain && ab < remain) { s_cut = (u32)tid; s_ge = ge; s_above = ab; }
        }
        __syncthreads();
        u32 total_ge = (MC - remain) + s_ge;
        thresh = ((prefix << 8) | s_cut) << shift;
        if (total_ge <= 512 || pass == 3) break;
        prefix = (prefix << 8) | s_cut;
        remain -= s_above;
        __syncthreads();
    }

    // ---- collect superset, key = (score_bits<<32) | ~anchor ----
    #pragma unroll
    for (int e = 0; e < 18; e++) {
        u32 u = ssc[e * 512 + tid];
        if (u >= thresh && u != 0) {
            u32 pos = atomicAdd(&s_cnt, 1);
            if (pos < 512)
                cand[pos] = ((u64)u << 32) | (u32)(~(u32)(e * 512 + tid));
        }
    }
    __syncthreads();
    u32 cnt = min(s_cnt, 512u);
    if ((u32)tid >= cnt) cand[tid] = 0;
    __syncthreads();

    // ---- hybrid bitonic sort 512 desc ----
    {
        u64 p = cand[tid];
        #pragma unroll
        for (int k = 2; k <= 32; k <<= 1)
            #pragma unroll
            for (int j = k >> 1; j; j >>= 1) {
                u64 q = __shfl_xor_sync(0xffffffffu, p, j);
                bool keep_max = ((tid & k) == 0) == ((tid & j) == 0);
                p = keep_max ? (p > q ? p : q) : (p < q ? p : q);
            }
        cand[tid] = p;
        __syncthreads();
        for (int k = 64; k <= 512; k <<= 1) {
            for (int j = k >> 1; j >= 32; j >>= 1) {
                int i = tid, x = i ^ j;
                if (x > i) {
                    u64 a2 = cand[i], b2 = cand[x];
                    bool sw = ((i & k) == 0) ? (a2 < b2) : (a2 > b2);
                    if (sw) { cand[i] = b2; cand[x] = a2; }
                }
                __syncthreads();
            }
            p = cand[tid];
            #pragma unroll
            for (int j = 16; j; j >>= 1) {
                u64 q = __shfl_xor_sync(0xffffffffu, p, j);
                bool keep_max = ((tid & k) == 0) == ((tid & j) == 0);
                p = keep_max ? (p > q ? p : q) : (p < q ? p : q);
            }
            cand[tid] = p;
            __syncthreads();
        }
    }
    int M = min((int)cnt, MC);

    // ---- NMS state aliases dead score buffer ----
    u32*    ssup  = (u32*)buf;                   // [300][10]  : 0..12000
    float4* sbox  = (float4*)(buf + 12032);      // [301]      : ..16848
    float*  sarea = (float*)(buf + 16864);       // [301]      : ..18068
    u32*    smu   = (u32*)(buf + 18080);         // [300] score bits by rank
    u32*    smn   = (u32*)(buf + 19296);         // [300] anchor by rank

    // zero suppression matrix
    #pragma unroll
    for (int k2 = tid; k2 < MC * 10; k2 += 512) ssup[k2] = 0;

    if (tid < M) {
        u64 key = cand[tid];
        u32 ub = (u32)(key >> 32);
        u32 an = ~(u32)key;
        smu[tid] = ub;
        smn[tid] = an;
        const float4 bx = *(const float4*)(in + ((size_t)b * NANCH + an) * ROWD + 600);
        // bx = (cx, cy, w, h) -> exact reference corner encode
        float y0 = __fsub_rn(bx.y, __fmul_rn(bx.w, 0.5f));
        float x0 = __fsub_rn(bx.x, __fmul_rn(bx.z, 0.5f));
        float y1 = __fadd_rn(bx.y, __fmul_rn(bx.w, 0.5f));
        float x1 = __fadd_rn(bx.x, __fmul_rn(bx.z, 0.5f));
        sbox[tid]  = make_float4(y0, x0, y1, x1);
        sarea[tid] = __fmul_rn(__fsub_rn(y1, y0), __fsub_rn(x1, x0));
    }
    __syncthreads();

    // ---- triangular suppression matrix, even pair distribution ----
    int npairs = (M * (M - 1)) >> 1;
    int pp = (npairs + 511) >> 9;                 // pairs per thread
    int k0 = tid * pp;
    int k1 = min(k0 + pp, npairs);
    if (k0 < k1) {
        int i = (int)(__fmul_rn(0.5f, __fadd_rn(1.0f, sqrtf((float)(8 * k0 + 1)))));
        if (i < 1) i = 1;
        while ((i * (i - 1)) >> 1 > k0) i--;
        while (k0 >= ((i * (i + 1)) >> 1)) i++;
        int j = k0 - ((i * (i - 1)) >> 1);
        float4 bi = sbox[i];
        float  aI = sarea[i];
        for (int k2 = k0; k2 < k1; k2++) {
            float4 bj = sbox[j];
            float  aj = sarea[j];
            if (iou_gt(bi.x, bi.y, bi.z, bi.w, aI, bj, aj))
                atomicOr(&ssup[i * 10 + (j >> 5)], 1u << (j & 31));
            if (++j == i) { j = 0; i++; bi = sbox[i]; aI = sarea[i]; }
        }
    }
    __syncthreads();

    // ---- warp-cooperative serial greedy resolve ----
    if (tid < 32) {
        u32 kreg = 0;
        for (int r = 0; r < M; r++) {
            u32 row = (lane < 10) ? ssup[r * 10 + lane] : 0u;
            bool sup = __any_sync(0xffffffffu, (row & kreg) != 0u);
            if (!sup && lane == (r >> 5)) kreg |= 1u << (r & 31);
        }
        if (lane < 10) keepw[lane] = kreg;
    }
    __syncthreads();

    // ---- append kept candidates above the provably-safe global cutoff ----
    if (tid < M && ((keepw[tid >> 5] >> (tid & 31)) & 1u)) {
        u64 gkey = ((u64)smu[tid] << 32) | (u32)(~(u32)(c * MC + tid));
        if (gkey >= s_tkey) {
            u32 p2 = atomicAdd(&g_cnt[b], 1u);
            if (p2 < CAP) { g_key[b * CAP + p2] = gkey; g_aux[b * CAP + p2] = smn[tid]; }
        }
    }
}

// --------------------- final: top-200 by key, re-encode ----------------------
__global__ void __launch_bounds__(1024, 1) k_final(const float* __restrict__ in,
                                                   float* __restrict__ out) {
    __shared__ u64 skey[1024];
    __shared__ u32 saux[1024];
    int b = blockIdx.x, tid = threadIdx.x;
    u32 n = min(min(g_cnt[b], (u32)CAP), 1024u);
    u64 p = 0; u32 pa = 0;
    if ((u32)tid < n) { p = g_key[b * CAP + tid]; pa = g_aux[b * CAP + tid]; }
    // hybrid bitonic 1024 desc with aux
    #pragma unroll
    for (int k = 2; k <= 32; k <<= 1)
        #pragma unroll
        for (int j = k >> 1; j; j >>= 1) {
            u64 q = __shfl_xor_sync(0xffffffffu, p, j);
            u32 qa = __shfl_xor_sync(0xffffffffu, pa, j);
            bool keep_max = ((tid & k) == 0) == ((tid & j) == 0);
            bool sw = keep_max ? (q > p) : (q < p);
            if (sw) { p = q; pa = qa; }
        }
    skey[tid] = p; saux[tid] = pa;
    __syncthreads();
    for (int k = 64; k <= 1024; k <<= 1) {
        for (int j = k >> 1; j >= 32; j >>= 1) {
            int i = tid, x = i ^ j;
            if (x > i) {
                u64 u1 = skey[i], u2 = skey[x];
                bool sw = ((i & k) == 0) ? (u1 < u2) : (u1 > u2);
                if (sw) {
                    skey[i] = u2; skey[x] = u1;
                    u32 t2 = saux[i]; saux[i] = saux[x]; saux[x] = t2;
                }
            }
            __syncthreads();
        }
        p = skey[tid]; pa = saux[tid];
        #pragma unroll
        for (int j = 16; j; j >>= 1) {
            u64 q = __shfl_xor_sync(0xffffffffu, p, j);
            u32 qa = __shfl_xor_sync(0xffffffffu, pa, j);
            bool keep_max = ((tid & k) == 0) == ((tid & j) == 0);
            bool sw = keep_max ? (q > p) : (q < p);
            if (sw) { p = q; pa = qa; }
        }
        skey[tid] = p; saux[tid] = pa;
        __syncthreads();
    }

    if (tid < 200) {
        u64 key = skey[tid];
        float cls = 0.f, score = 0.f, ocx = 0.f, ocy = 0.f, otw = 0.f, oth = 0.f;
        if (key) {
            score = __uint_as_float((u32)(key >> 32));
            u32 flat = ~(u32)key;
            cls = (float)(flat / MC + 1);
            u32 anchor = saux[tid];
            const float4 bx = *(const float4*)(in + ((size_t)b * NANCH + anchor) * ROWD + 600);
            float y0 = __fsub_rn(bx.y, __fmul_rn(bx.w, 0.5f));
            float x0 = __fsub_rn(bx.x, __fmul_rn(bx.z, 0.5f));
            float y1 = __fadd_rn(bx.y, __fmul_rn(bx.w, 0.5f));
            float x1 = __fadd_rn(bx.x, __fmul_rn(bx.z, 0.5f));
            otw = __fsub_rn(x1, x0);
            oth = __fsub_rn(y1, y0);
            ocx = __fadd_rn(x0, __fmul_rn(otw, 0.5f));
            ocy = __fadd_rn(y0, __fmul_rn(oth, 0.5f));
        }
        float* o = out + ((size_t)b * 200 + tid) * 6;
        o[0] = cls; o[1] = score; o[2] = ocx; o[3] = ocy; o[4] = otw; o[5] = oth;
    }
}

// ------------------------------------------------------------------------------
extern "C" void kernel_launch(void* const* d_in, const int* in_sizes, int n_in,
                              void* d_out, int out_size) {
    const float* in = (const float*)d_in[0];
    float* out = (float*)d_out;

    k_reset<<<2, 1024>>>();
    k_prep<<<dim3((NANCH + 63) / 64, (NCLS + 63) / 64, 2), 512>>>(in);
    k_thresh<<<2, 1024>>>();
    k_perclass<<<dim3(NCLS, 2), 512>>>(in);
    k_final<<<2, 1024>>>(in, out);
}

// round 8
// speedup vs baseline: 1.1474x; 1.1474x over previous
#include <cuda_runtime.h>

#define NANCH 8732
#define NPAD  8736
#define NCLS  599
#define MC    300
#define CAP   4096
#define ROWD  604

typedef unsigned int u32;
typedef unsigned long long u64;

// ------------------- static device scratch (no allocations) -------------------
__device__ u32   g_sbits[2u * NCLS * NPAD];      // [B, C, Npad] masked score bits (pad stays 0)
__device__ u32   g_clsmax[2 * NCLS];             // per-class max score bits
__device__ u64   g_tkey[2];                      // global cutoff key per image
__device__ u64   g_key[2 * CAP];                 // compacted kept keys
__device__ u32   g_aux[2 * CAP];                 // anchor ids parallel to g_key
__device__ u32   g_cnt[2];                       // per-image append counters

// ------------------------------- reset ---------------------------------------
__global__ void k_reset() {
    int t = blockIdx.x * blockDim.x + threadIdx.x;
    if (t < 2) g_cnt[t] = 0;
    if (t < 2 * NCLS) g_clsmax[t] = 0;
}

// ---- streaming transpose: 64 anchors x 64 classes per CTA, masked bits out ----
__global__ void __launch_bounds__(512) k_prep(const float* __restrict__ in) {
    __shared__ float t[64][65];
    int b  = blockIdx.z;
    int n0 = blockIdx.x * 64;
    int c0 = blockIdx.y * 64;
    int tid = threadIdx.x, lane = tid & 31, w = tid >> 5;   // 16 warps

    #pragma unroll
    for (int r = 0; r < 4; r++) {
        int row = w * 4 + r;
        int n = n0 + row;
        float v0 = 0.f, v1 = 0.f;
        if (n < NANCH) {
            const float* src = in + ((size_t)b * NANCH + n) * ROWD + 1 + c0;
            if (c0 + lane < NCLS)      v0 = __ldg(&src[lane]);
            if (c0 + 32 + lane < NCLS) v1 = __ldg(&src[32 + lane]);
        }
        t[row][lane]      = v0;
        t[row][lane + 32] = v1;
    }
    __syncthreads();

    #pragma unroll
    for (int s = 0; s < 4; s++) {
        int cl  = s * 16 + w;
        int cgl = c0 + cl;
        float v0 = t[lane][cl];          // stride 65: conflict-free
        float v1 = t[lane + 32][cl];
        if (cgl < NCLS) {
            u32* dst = g_sbits + ((size_t)b * NCLS + cgl) * NPAD + n0;
            if (n0 + lane < NANCH)
                dst[lane]      = (v0 > 0.01f) ? __float_as_uint(v0) : 0u;
            if (n0 + 32 + lane < NANCH)
                dst[lane + 32] = (v1 > 0.01f) ? __float_as_uint(v1) : 0u;
        }
        float mx = fmaxf(v0, v1);
        #pragma unroll
        for (int off = 16; off; off >>= 1)
            mx = fmaxf(mx, __shfl_xor_sync(0xffffffffu, mx, off));
        if (lane == 0 && cgl < NCLS)
            atomicMax(&g_clsmax[b * NCLS + cgl], __float_as_uint(mx));
    }
}

// ------------- per-image cutoff = 200th largest class-max key ----------------
__global__ void __launch_bounds__(1024, 1) k_thresh() {
    __shared__ u64 a[1024];
    int b = blockIdx.x, tid = threadIdx.x;
    u64 p = 0;
    if (tid < NCLS) {
        u32 mb = g_clsmax[b * NCLS + tid];
        if (__uint_as_float(mb) > 0.01f)
            p = ((u64)mb << 32) | (u32)(~(u32)(tid * MC));
    }
    #pragma unroll
    for (int k = 2; k <= 32; k <<= 1)
        #pragma unroll
        for (int j = k >> 1; j; j >>= 1) {
            u64 q = __shfl_xor_sync(0xffffffffu, p, j);
            bool keep_max = ((tid & k) == 0) == ((tid & j) == 0);
            bool sw = keep_max ? (q > p) : (q < p);
            if (sw) p = q;
        }
    a[tid] = p;
    __syncthreads();
    for (int k = 64; k <= 1024; k <<= 1) {
        for (int j = k >> 1; j >= 32; j >>= 1) {
            int i = tid, x = i ^ j;
            if (x > i) {
                u64 u1 = a[i], u2 = a[x];
                bool sw = ((i & k) == 0) ? (u1 < u2) : (u1 > u2);
                if (sw) { a[i] = u2; a[x] = u1; }
            }
            __syncthreads();
        }
        p = a[tid];
        #pragma unroll
        for (int j = 16; j; j >>= 1) {
            u64 q = __shfl_xor_sync(0xffffffffu, p, j);
            bool keep_max = ((tid & k) == 0) == ((tid & j) == 0);
            bool sw = keep_max ? (q > p) : (q < p);
            if (sw) p = q;
        }
        a[tid] = p;
        __syncthreads();
    }
    if (tid == 0) g_tkey[b] = a[199];
}

// -------- exact IoU>0.45 predicate with guarded div-free fast path -----------
__device__ __forceinline__ bool iou_gt(float y0, float x0, float y1, float x1, float a,
                                       float4 bj, float aj) {
    float ih = fmaxf(__fsub_rn(fminf(y1, bj.z), fmaxf(y0, bj.x)), 0.f);
    float iw = fmaxf(__fsub_rn(fminf(x1, bj.w), fmaxf(x0, bj.y)), 0.f);
    float inter = __fmul_rn(ih, iw);
    float uni   = __fsub_rn(__fadd_rn(a, aj), inter);
    if (!(uni > 0.f)) return false;
    float t = __fmul_rn(uni, 0.45f);
    if (inter > __fmul_rn(t, 1.000002f)) return true;
    if (inter < __fmul_rn(t, 0.999998f)) return false;
    return __fdiv_rn(inter, uni) > 0.45f;
}

// --------------- per-(b,c): top-300 select, tile NMS, filtered append ---------
__global__ void __launch_bounds__(512, 4) k_perclass(const float* __restrict__ in) {
    __shared__ __align__(16) char buf[9216 * 4];   // score bits, later NMS state
    __shared__ u32 hist[256], suf[256], wtot[8];
    __shared__ u64 cand[512];
    __shared__ float4 tbox[64];
    __shared__ float  tarea[64];
    __shared__ u64    tsup[64];
    __shared__ u32    wcnt[16];
    __shared__ u32 s_cnt, s_cut, s_ge, s_above;
    __shared__ u64 s_tkey, s_kmask;

    int c = blockIdx.x, b = blockIdx.y;
    int tid = threadIdx.x, lane = tid & 31, wid = tid >> 5;

    u32*   ssc  = (u32*)buf;
    uint4* ssc4 = (uint4*)buf;
    const uint4* sb4 = (const uint4*)&g_sbits[((size_t)b * NCLS + c) * NPAD];

    if (tid < 256) hist[tid] = 0;
    if (tid == 0) { s_cnt = 0; s_tkey = g_tkey[b]; }
    __syncthreads();

    // ---- fused vectorized stage + radix pass-0 histogram (NPAD/4 = 2184) ----
    #pragma unroll
    for (int e = 0; e < 5; e++) {
        int i4 = e * 512 + tid;
        if (i4 < 2184) {
            uint4 v = __ldg(&sb4[i4]);
            ssc4[i4] = v;
            #pragma unroll
            for (int s = 0; s < 4; s++) {
                u32 u = (s == 0) ? v.x : (s == 1) ? v.y : (s == 2) ? v.z : v.w;
                int bin = u >> 24;
                u32 grp = __match_any_sync(__activemask(), bin);
                if ((grp & ((1u << lane) - 1u)) == 0u)
                    atomicAdd(&hist[bin], __popc(grp));
            }
        }
    }
    __syncthreads();

    // ---- radix select, early exit when superset fits in 512 ----
    u32 prefix = 0, remain = MC, thresh = 0;
    for (int pass = 0; pass < 4; pass++) {
        int shift = 24 - 8 * pass;
        if (pass > 0) {
            if (tid < 256) hist[tid] = 0;
            __syncthreads();
            #pragma unroll
            for (int e = 0; e < 5; e++) {
                int i4 = e * 512 + tid;
                if (i4 < 2184) {
                    uint4 v = ssc4[i4];
                    #pragma unroll
                    for (int s = 0; s < 4; s++) {
                        u32 u = (s == 0) ? v.x : (s == 1) ? v.y : (s == 2) ? v.z : v.w;
                        bool part = (u >> (shift + 8)) == prefix;
                        int bin = (u >> shift) & 0xFF;
                        int key = part ? bin : 999;
                        u32 grp = __match_any_sync(__activemask(), key);
                        if (part && (grp & ((1u << lane) - 1u)) == 0u)
                            atomicAdd(&hist[bin], __popc(grp));
                    }
                }
            }
            __syncthreads();
        }
        if (tid < 256) {
            u32 v = hist[tid];
            #pragma unroll
            for (int off = 1; off < 32; off <<= 1) {
                u32 o = __shfl_down_sync(0xffffffffu, v, off);
                if (lane + off < 32) v += o;
            }
            if (lane == 0) wtot[wid] = v;
            suf[tid] = v;
        }
        __syncthreads();
        if (tid < 256) {
            u32 add = 0;
            #pragma unroll
            for (int w2 = 0; w2 < 8; w2++)
                if (w2 > wid) add += wtot[w2];
            suf[tid] += add;
        }
        if (tid == 0) { s_cut = 0; s_ge = 0; s_above = 0; }
        __syncthreads();
        if (tid == 0 && suf[0] < remain) s_ge = suf[0];   // shortfall default
        if (tid < 256) {
            u32 ge = suf[tid];
            u32 ab = (tid == 255) ? 0u : suf[tid + 1];
            if (ge >= remain && ab < remain) { s_cut = (u32)tid; s_ge = ge; s_above = ab; }
        }
        __syncthreads();
        u32 total_ge = (MC - remain) + s_ge;
        thresh = ((prefix << 8) | s_cut) << shift;
        if (total_ge <= 512 || pass == 3) break;
        prefix = (prefix << 8) | s_cut;
        remain -= s_above;
        __syncthreads();
    }

    // ---- vectorized collect of superset, key = (score_bits<<32) | ~anchor ----
    #pragma unroll
    for (int e = 0; e < 5; e++) {
        int i4 = e * 512 + tid;
        if (i4 < 2184) {
            uint4 v = ssc4[i4];
            #pragma unroll
            for (int s = 0; s < 4; s++) {
                u32 u = (s == 0) ? v.x : (s == 1) ? v.y : (s == 2) ? v.z : v.w;
                if (u >= thresh && u != 0) {
                    u32 pos = atomicAdd(&s_cnt, 1);
                    if (pos < 512)
                        cand[pos] = ((u64)u << 32) | (u32)(~(u32)(i4 * 4 + s));
                }
            }
        }
    }
    __syncthreads();
    u32 cnt = min(s_cnt, 512u);
    if ((u32)tid >= cnt) cand[tid] = 0;
    __syncthreads();

    // ---- hybrid bitonic sort 512 desc ----
    {
        u64 p = cand[tid];
        #pragma unroll
        for (int k = 2; k <= 32; k <<= 1)
            #pragma unroll
            for (int j = k >> 1; j; j >>= 1) {
                u64 q = __shfl_xor_sync(0xffffffffu, p, j);
                bool keep_max = ((tid & k) == 0) == ((tid & j) == 0);
                p = keep_max ? (p > q ? p : q) : (p < q ? p : q);
            }
        cand[tid] = p;
        __syncthreads();
        for (int k = 64; k <= 512; k <<= 1) {
            for (int j = k >> 1; j >= 32; j >>= 1) {
                int i = tid, x = i ^ j;
                if (x > i) {
                    u64 a2 = cand[i], b2 = cand[x];
                    bool sw = ((i & k) == 0) ? (a2 < b2) : (a2 > b2);
                    if (sw) { cand[i] = b2; cand[x] = a2; }
                }
                __syncthreads();
            }
            p = cand[tid];
            #pragma unroll
            for (int j = 16; j; j >>= 1) {
                u64 q = __shfl_xor_sync(0xffffffffu, p, j);
                bool keep_max = ((tid & k) == 0) == ((tid & j) == 0);
                p = keep_max ? (p > q ? p : q) : (p < q ? p : q);
            }
            cand[tid] = p;
            __syncthreads();
        }
    }
    int M = min((int)cnt, MC);

    // ---- NMS state aliases dead score buffer ----
    float4* stb = (float4*)buf;                 // [320] compaction boxes
    float*  sta = (float*)(buf + 5120);         // [320] areas
    u32*    stp = (u32*)(buf + 6400);           // [320] original sorted rank
    u32*    smu = (u32*)(buf + 7680);           // [320] score bits by rank (fixed)
    u32*    smn = (u32*)(buf + 8960);           // [320] anchor by rank (fixed)

    float y0i = 0, x0i = 0, y1i = 0, x1i = 0, ai = 0;
    u32 pos = (u32)tid;
    bool alive = tid < M;
    if (alive) {
        u64 key = cand[tid];
        u32 ub = (u32)(key >> 32);
        u32 an = ~(u32)key;
        smu[tid] = ub;
        smn[tid] = an;
        const float4 bx = *(const float4*)(in + ((size_t)b * NANCH + an) * ROWD + 600);
        // bx = (cx, cy, w, h) -> exact reference corner encode
        y0i = __fsub_rn(bx.y, __fmul_rn(bx.w, 0.5f));
        x0i = __fsub_rn(bx.x, __fmul_rn(bx.z, 0.5f));
        y1i = __fadd_rn(bx.y, __fmul_rn(bx.w, 0.5f));
        x1i = __fadd_rn(bx.x, __fmul_rn(bx.z, 0.5f));
        ai  = __fmul_rn(__fsub_rn(y1i, y0i), __fsub_rn(x1i, x0i));
    }

    // ---- compacted tile-greedy NMS, 64 candidates finalized per round ----
    int total = M;
    while (total > 0) {
        int nt = min(total, 64);
        if (tid < nt) { tbox[tid] = make_float4(y0i, x0i, y1i, x1i); tarea[tid] = ai; }
        __syncthreads();
        u64 msup = 0;
        if (alive) {
            int jm = (tid < nt) ? tid : nt;
            for (int j = 0; j < jm; j++)
                msup |= ((u64)iou_gt(y0i, x0i, y1i, x1i, ai, tbox[j], tarea[j])) << j;
        }
        if (tid < nt) tsup[tid] = msup;
        __syncthreads();
        if (tid == 0) {
            u64 km = 0;
            for (int k2 = 0; k2 < nt; k2++)
                if ((tsup[k2] & km) == 0ull) km |= 1ull << k2;
            s_kmask = km;
        }
        __syncthreads();
        u64 km = s_kmask;
        if (alive) {
            if (tid < nt) {
                if ((km >> tid) & 1ull) {
                    u64 gkey = ((u64)smu[pos] << 32) | (u32)(~(u32)(c * MC + pos));
                    if (gkey >= s_tkey) {
                        u32 p2 = atomicAdd(&g_cnt[b], 1u);
                        if (p2 < CAP) { g_key[b * CAP + p2] = gkey; g_aux[b * CAP + p2] = smn[pos]; }
                    }
                }
                alive = false;                    // tile members finalized
            } else if (msup & km) {
                alive = false;                    // suppressed by a kept tile member
            }
        }
        // compact survivors to thread front (preserves sorted order)
        u32 wb = __ballot_sync(0xffffffffu, alive);
        if (lane == 0) wcnt[wid] = wb;
        __syncthreads();
        int newtotal = 0, before = 0;
        #pragma unroll
        for (int w2 = 0; w2 < 16; w2++) {
            int p2 = __popc(wcnt[w2]);
            newtotal += p2;
            if (w2 < wid) before += p2;
        }
        if (alive) {
            int r = before + __popc(wb & ((1u << lane) - 1u));
            stb[r] = make_float4(y0i, x0i, y1i, x1i);
            sta[r] = ai;
            stp[r] = pos;
        }
        __syncthreads();
        alive = tid < newtotal;
        if (alive) {
            float4 bx = stb[tid];
            y0i = bx.x; x0i = bx.y; y1i = bx.z; x1i = bx.w;
            ai = sta[tid]; pos = stp[tid];
        }
        total = newtotal;
        __syncthreads();
    }
}

// --------------------- final: top-200 by key, re-encode ----------------------
__global__ void __launch_bounds__(1024, 1) k_final(const float* __restrict__ in,
                                                   float* __restrict__ out) {
    __shared__ u64 skey[1024];
    __shared__ u32 saux[1024];
    int b = blockIdx.x, tid = threadIdx.x;
    u32 n = min(min(g_cnt[b], (u32)CAP), 1024u);
    u64 p = 0; u32 pa = 0;
    if ((u32)tid < n) { p = g_key[b * CAP + tid]; pa = g_aux[b * CAP + tid]; }
    #pragma unroll
    for (int k = 2; k <= 32; k <<= 1)
        #pragma unroll
        for (int j = k >> 1; j; j >>= 1) {
            u64 q = __shfl_xor_sync(0xffffffffu, p, j);
            u32 qa = __shfl_xor_sync(0xffffffffu, pa, j);
            bool keep_max = ((tid & k) == 0) == ((tid & j) == 0);
            bool sw = keep_max ? (q > p) : (q < p);
            if (sw) { p = q; pa = qa; }
        }
    skey[tid] = p; saux[tid] = pa;
    __syncthreads();
    for (int k = 64; k <= 1024; k <<= 1) {
        for (int j = k >> 1; j >= 32; j >>= 1) {
            int i = tid, x = i ^ j;
            if (x > i) {
                u64 u1 = skey[i], u2 = skey[x];
                bool sw = ((i & k) == 0) ? (u1 < u2) : (u1 > u2);
                if (sw) {
                    skey[i] = u2; skey[x] = u1;
                    u32 t2 = saux[i]; saux[i] = saux[x]; saux[x] = t2;
                }
            }
            __syncthreads();
        }
        p = skey[tid]; pa = saux[tid];
        #pragma unroll
        for (int j = 16; j; j >>= 1) {
            u64 q = __shfl_xor_sync(0xffffffffu, p, j);
            u32 qa = __shfl_xor_sync(0xffffffffu, pa, j);
            bool keep_max = ((tid & k) == 0) == ((tid & j) == 0);
            bool sw = keep_max ? (q > p) : (q < p);
            if (sw) { p = q; pa = qa; }
        }
        skey[tid] = p; saux[tid] = pa;
        __syncthreads();
    }

    if (tid < 200) {
        u64 key = skey[tid];
        float cls = 0.f, score = 0.f, ocx = 0.f, ocy = 0.f, otw = 0.f, oth = 0.f;
        if (key) {
            score = __uint_as_float((u32)(key >> 32));
            u32 flat = ~(u32)key;
            cls = (float)(flat / MC + 1);
            u32 anchor = saux[tid];
            const float4 bx = *(const float4*)(in + ((size_t)b * NANCH + anchor) * ROWD + 600);
            float y0 = __fsub_rn(bx.y, __fmul_rn(bx.w, 0.5f));
            float x0 = __fsub_rn(bx.x, __fmul_rn(bx.z, 0.5f));
            float y1 = __fadd_rn(bx.y, __fmul_rn(bx.w, 0.5f));
            float x1 = __fadd_rn(bx.x, __fmul_rn(bx.z, 0.5f));
            otw = __fsub_rn(x1, x0);
            oth = __fsub_rn(y1, y0);
            ocx = __fadd_rn(x0, __fmul_rn(otw, 0.5f));
            ocy = __fadd_rn(y0, __fmul_rn(oth, 0.5f));
        }
        float* o = out + ((size_t)b * 200 + tid) * 6;
        o[0] = cls; o[1] = score; o[2] = ocx; o[3] = ocy; o[4] = otw; o[5] = oth;
    }
}

// ------------------------------------------------------------------------------
extern "C" void kernel_launch(void* const* d_in, const int* in_sizes, int n_in,
                              void* d_out, int out_size) {
    const float* in = (const float*)d_in[0];
    float* out = (float*)d_out;

    k_reset<<<2, 1024>>>();
    k_prep<<<dim3((NANCH + 63) / 64, (NCLS + 63) / 64, 2), 512>>>(in);
    k_thresh<<<2, 1024>>>();
    k_perclass<<<dim3(NCLS, 2), 512>>>(in);
    k_final<<<2, 1024>>>(in, out);
}

// round 9
// speedup vs baseline: 4.1307x; 3.6000x over previous
#include <cuda_runtime.h>

#define NANCH 8732
#define NCLS  599
#define MC    300
#define CAPN  1024
#define ROWD  604

typedef unsigned int u32;
typedef unsigned long long u64;

// ------------------- static device scratch (no allocations) -------------------
__device__ u32 g_clsmax[2 * NCLS];     // per-class max score bits
__device__ u64 g_tkey[2];              // global cutoff key per image
__device__ u64 g_col[2 * CAPN];        // collected candidate sortkeys
__device__ u32 g_ccnt[2];              // per-image collected counters

// ------------------------------- reset ---------------------------------------
__global__ void k_reset() {
    int t = blockIdx.x * blockDim.x + threadIdx.x;
    if (t < 2) g_ccnt[t] = 0;
    if (t < 2 * NCLS) g_clsmax[t] = 0;
}

// --------------- per-class max: coalesced scan of raw input ------------------
__global__ void __launch_bounds__(256) k_clsmax(const float* __restrict__ in) {
    int b  = blockIdx.y;
    int a0 = blockIdx.x * 32;
    int a1 = min(a0 + 32, NANCH);
    int t  = threadIdx.x;
    float m0 = 0.f, m1 = 0.f, m2 = 0.f;
    #pragma unroll 4
    for (int a = a0; a < a1; a++) {
        const float* row = in + ((size_t)b * NANCH + a) * ROWD + 1;
        m0 = fmaxf(m0, __ldg(&row[t]));
        m1 = fmaxf(m1, __ldg(&row[t + 256]));
        if (t < NCLS - 512) m2 = fmaxf(m2, __ldg(&row[t + 512]));
    }
    atomicMax(&g_clsmax[b * NCLS + t],       __float_as_uint(m0));
    atomicMax(&g_clsmax[b * NCLS + t + 256], __float_as_uint(m1));
    if (t < NCLS - 512)
        atomicMax(&g_clsmax[b * NCLS + t + 512], __float_as_uint(m2));
}

// ------------- hybrid bitonic 1024 desc (shfl j<=16, smem j>=32) --------------
__device__ __forceinline__ u64 sort1024_desc(u64 p, u64* sm, int tid) {
    #pragma unroll
    for (int k = 2; k <= 32; k <<= 1)
        #pragma unroll
        for (int j = k >> 1; j; j >>= 1) {
            u64 q = __shfl_xor_sync(0xffffffffu, p, j);
            bool keep_max = ((tid & k) == 0) == ((tid & j) == 0);
            bool sw = keep_max ? (q > p) : (q < p);
            if (sw) p = q;
        }
    sm[tid] = p;
    __syncthreads();
    for (int k = 64; k <= 1024; k <<= 1) {
        for (int j = k >> 1; j >= 32; j >>= 1) {
            int x = tid ^ j;
            if (x > tid) {
                u64 a = sm[tid], bb = sm[x];
                bool sw = ((tid & k) == 0) ? (a < bb) : (a > bb);
                if (sw) { sm[tid] = bb; sm[x] = a; }
            }
            __syncthreads();
        }
        p = sm[tid];
        #pragma unroll
        for (int j = 16; j; j >>= 1) {
            u64 q = __shfl_xor_sync(0xffffffffu, p, j);
            bool keep_max = ((tid & k) == 0) == ((tid & j) == 0);
            bool sw = keep_max ? (q > p) : (q < p);
            if (sw) p = q;
        }
        sm[tid] = p;
        __syncthreads();
    }
    return p;
}

// ------------- per-image cutoff = 200th largest class-max key ----------------
__global__ void __launch_bounds__(1024, 1) k_thresh() {
    __shared__ u64 a[1024];
    int b = blockIdx.x, tid = threadIdx.x;
    u64 p = 0;
    if (tid < NCLS) {
        u32 mb = g_clsmax[b * NCLS + tid];
        if (__uint_as_float(mb) > 0.01f)
            p = ((u64)mb << 32) | (u32)(~(u32)(tid * MC));
    }
    sort1024_desc(p, a, tid);
    if (tid == 0) g_tkey[b] = a[199];
}

// -------- collect all (class, anchor) with score bits >= cutoff-hi ------------
__global__ void __launch_bounds__(256) k_collect(const float* __restrict__ in) {
    int b  = blockIdx.y;
    int a0 = blockIdx.x * 32;
    int a1 = min(a0 + 32, NANCH);
    int t  = threadIdx.x;
    u32 th = (u32)(g_tkey[b] >> 32);
    if (th < 0x3C23D70Bu) th = 0x3C23D70Bu;    // never below "> 0.01f"
    for (int a = a0; a < a1; a++) {
        const float* row = in + ((size_t)b * NANCH + a) * ROWD + 1;
        #pragma unroll
        for (int s = 0; s < 3; s++) {
            int c = t + s * 256;
            if (c < NCLS) {
                float v = __ldg(&row[c]);
                u32 ub = __float_as_uint(v);
                if (v > 0.01f && ub >= th) {
                    u32 p = atomicAdd(&g_ccnt[b], 1u);
                    if (p < CAPN)
                        g_col[b * CAPN + p] =
                            ((u64)c << 46) | ((u64)ub << 14) | (u64)(0x3FFFu - (u32)a);
                }
            }
        }
    }
}

// ---- final: sort candidates, per-class ranks + greedy NMS, top-200, encode ----
__global__ void __launch_bounds__(1024, 1) k_nms_final(const float* __restrict__ in,
                                                       float* __restrict__ out) {
    __shared__ u64    skey[1024];
    __shared__ float4 sbox[1024];
    __shared__ float  sarea[1024];
    __shared__ u32    skept[1024];
    __shared__ u32    saux[1024];

    int b = blockIdx.x, tid = threadIdx.x;
    u32 n = min(g_ccnt[b], (u32)CAPN);

    // ---- phase A: sort collected keys desc (class desc, score desc, anchor asc) ----
    u64 p = ((u32)tid < n) ? g_col[b * CAPN + tid] : 0ull;
    sort1024_desc(p, skey, tid);

    bool valid = (u32)tid < n;
    u32 c = 0, ub = 0, anch = 0;
    if (valid) {
        u64 key = skey[tid];
        c    = (u32)(key >> 46);
        ub   = (u32)(key >> 14);
        anch = 0x3FFFu - (u32)(key & 0x3FFFu);
        const float4 bx = *(const float4*)(in + ((size_t)b * NANCH + anch) * ROWD + 600);
        // bx = (cx, cy, w, h) -> exact reference corner encode
        float y0 = __fsub_rn(bx.y, __fmul_rn(bx.w, 0.5f));
        float x0 = __fsub_rn(bx.x, __fmul_rn(bx.z, 0.5f));
        float y1 = __fadd_rn(bx.y, __fmul_rn(bx.w, 0.5f));
        float x1 = __fadd_rn(bx.x, __fmul_rn(bx.z, 0.5f));
        sbox[tid]  = make_float4(y0, x0, y1, x1);
        sarea[tid] = __fmul_rn(__fsub_rn(y1, y0), __fsub_rn(x1, x0));
        skept[tid] = 0;
    }

    // rank within class = distance to segment start (segments are tiny)
    int r = 0;
    if (valid)
        while (tid - r - 1 >= 0 && (u32)(skey[tid - r - 1] >> 46) == c) r++;
    __syncthreads();

    // ---- per-class exact greedy NMS, one leader thread per class segment ----
    if (valid && r == 0) {
        skept[tid] = 1;
        for (int k = tid + 1; k < (int)n && (u32)(skey[k] >> 46) == c; k++) {
            float4 bk = sbox[k];
            float  ak = sarea[k];
            bool sup = false;
            for (int j = tid; j < k; j++) {
                if (skept[j]) {
                    float4 bj = sbox[j];
                    float ih = fmaxf(__fsub_rn(fminf(bj.z, bk.z), fmaxf(bj.x, bk.x)), 0.f);
                    float iw = fmaxf(__fsub_rn(fminf(bj.w, bk.w), fmaxf(bj.y, bk.y)), 0.f);
                    float inter = __fmul_rn(ih, iw);
                    float uni   = __fsub_rn(__fadd_rn(sarea[j], ak), inter);
                    if (uni > 0.f && __fdiv_rn(inter, uni) > 0.45f) { sup = true; break; }
                }
            }
            skept[k] = sup ? 0u : 1u;
        }
    }
    __syncthreads();

    // ---- build final keys: kept, in class top-300, above exact u64 cutoff ----
    u64 tk = g_tkey[b];
    u64 fk = 0; u32 pa = 0;
    if (valid && skept[tid] && r < MC) {
        u32 flat = c * MC + (u32)r;
        u64 cand = ((u64)ub << 32) | (u32)(~flat);
        if (cand >= tk) { fk = cand; pa = anch; }
    }
    __syncthreads();   // done reading skey/sbox before reuse

    // ---- phase B: sort (fk, anchor) desc, hybrid bitonic with aux ----
    p = fk;
    #pragma unroll
    for (int k = 2; k <= 32; k <<= 1)
        #pragma unroll
        for (int j = k >> 1; j; j >>= 1) {
            u64 q  = __shfl_xor_sync(0xffffffffu, p, j);
            u32 qa = __shfl_xor_sync(0xffffffffu, pa, j);
            bool keep_max = ((tid & k) == 0) == ((tid & j) == 0);
            bool sw = keep_max ? (q > p) : (q < p);
            if (sw) { p = q; pa = qa; }
        }
    skey[tid] = p; saux[tid] = pa;
    __syncthreads();
    for (int k = 64; k <= 1024; k <<= 1) {
        for (int j = k >> 1; j >= 32; j >>= 1) {
            int x = tid ^ j;
            if (x > tid) {
                u64 u1 = skey[tid], u2 = skey[x];
                bool sw = ((tid & k) == 0) ? (u1 < u2) : (u1 > u2);
                if (sw) {
                    skey[tid] = u2; skey[x] = u1;
                    u32 t2 = saux[tid]; saux[tid] = saux[x]; saux[x] = t2;
                }
            }
            __syncthreads();
        }
        p = skey[tid]; pa = saux[tid];
        #pragma unroll
        for (int j = 16; j; j >>= 1) {
            u64 q  = __shfl_xor_sync(0xffffffffu, p, j);
            u32 qa = __shfl_xor_sync(0xffffffffu, pa, j);
            bool keep_max = ((tid & k) == 0) == ((tid & j) == 0);
            bool sw = keep_max ? (q > p) : (q < p);
            if (sw) { p = q; pa = qa; }
        }
        skey[tid] = p; saux[tid] = pa;
        __syncthreads();
    }

    // ---- emit top-200 with exact corner -> center inverse transform ----
    if (tid < 200) {
        u64 key = skey[tid];
        float cls = 0.f, score = 0.f, ocx = 0.f, ocy = 0.f, otw = 0.f, oth = 0.f;
        if (key) {
            score = __uint_as_float((u32)(key >> 32));
            u32 flat = ~(u32)key;
            cls = (float)(flat / MC + 1);
            u32 anchor = saux[tid];
            const float4 bx = *(const float4*)(in + ((size_t)b * NANCH + anchor) * ROWD + 600);
            float y0 = __fsub_rn(bx.y, __fmul_rn(bx.w, 0.5f));
            float x0 = __fsub_rn(bx.x, __fmul_rn(bx.z, 0.5f));
            float y1 = __fadd_rn(bx.y, __fmul_rn(bx.w, 0.5f));
            float x1 = __fadd_rn(bx.x, __fmul_rn(bx.z, 0.5f));
            otw = __fsub_rn(x1, x0);
            oth = __fsub_rn(y1, y0);
            ocx = __fadd_rn(x0, __fmul_rn(otw, 0.5f));
            ocy = __fadd_rn(y0, __fmul_rn(oth, 0.5f));
        }
        float* o = out + ((size_t)b * 200 + tid) * 6;
        o[0] = cls; o[1] = score; o[2] = ocx; o[3] = ocy; o[4] = otw; o[5] = oth;
    }
}

// ------------------------------------------------------------------------------
extern "C" void kernel_launch(void* const* d_in, const int* in_sizes, int n_in,
                              void* d_out, int out_size) {
    const float* in = (const float*)d_in[0];
    float* out = (float*)d_out;

    k_reset<<<2, 1024>>>();
    k_clsmax<<<dim3(273, 2), 256>>>(in);
    k_thresh<<<2, 1024>>>();
    k_collect<<<dim3(273, 2), 256>>>(in);
    k_nms_final<<<2, 1024>>>(in, out);
}

// round 10
// speedup vs baseline: 5.4192x; 1.3119x over previous
#include <cuda_runtime.h>

#define NANCH 8732
#define NCLS  599
#define MC    300
#define CAPN  1024
#define ROWD  604

typedef unsigned int u32;
typedef unsigned long long u64;

// ------------------- static device scratch (no allocations) -------------------
__device__ u32 g_clsmax[2 * NCLS];     // per-class max score bits
__device__ u64 g_tkey[2];              // global cutoff key per image
__device__ u64 g_col[2 * CAPN];        // collected candidate sortkeys
__device__ u32 g_ccnt[2];              // per-image collected counters

// ------------------------------- reset ---------------------------------------
__global__ void k_reset() {
    int t = blockIdx.x * blockDim.x + threadIdx.x;
    if (t < 2) g_ccnt[t] = 0;
    if (t < 2 * NCLS) g_clsmax[t] = 0;
}

// --------------- per-class max: coalesced scan of raw input ------------------
__global__ void __launch_bounds__(256) k_clsmax(const float* __restrict__ in) {
    int b  = blockIdx.y;
    int a0 = blockIdx.x * 32;
    int a1 = min(a0 + 32, NANCH);
    int t  = threadIdx.x;
    float m0 = 0.f, m1 = 0.f, m2 = 0.f;
    #pragma unroll 4
    for (int a = a0; a < a1; a++) {
        const float* row = in + ((size_t)b * NANCH + a) * ROWD + 1;
        m0 = fmaxf(m0, __ldg(&row[t]));
        m1 = fmaxf(m1, __ldg(&row[t + 256]));
        if (t < NCLS - 512) m2 = fmaxf(m2, __ldg(&row[t + 512]));
    }
    atomicMax(&g_clsmax[b * NCLS + t],       __float_as_uint(m0));
    atomicMax(&g_clsmax[b * NCLS + t + 256], __float_as_uint(m1));
    if (t < NCLS - 512)
        atomicMax(&g_clsmax[b * NCLS + t + 512], __float_as_uint(m2));
}

// ------------- hybrid bitonic 1024 desc (shfl j<=16, smem j>=32) --------------
__device__ __forceinline__ u64 sort1024_desc(u64 p, u64* sm, int tid) {
    #pragma unroll
    for (int k = 2; k <= 32; k <<= 1)
        #pragma unroll
        for (int j = k >> 1; j; j >>= 1) {
            u64 q = __shfl_xor_sync(0xffffffffu, p, j);
            bool keep_max = ((tid & k) == 0) == ((tid & j) == 0);
            bool sw = keep_max ? (q > p) : (q < p);
            if (sw) p = q;
        }
    sm[tid] = p;
    __syncthreads();
    for (int k = 64; k <= 1024; k <<= 1) {
        for (int j = k >> 1; j >= 32; j >>= 1) {
            int x = tid ^ j;
            if (x > tid) {
                u64 a = sm[tid], bb = sm[x];
                bool sw = ((tid & k) == 0) ? (a < bb) : (a > bb);
                if (sw) { sm[tid] = bb; sm[x] = a; }
            }
            __syncthreads();
        }
        p = sm[tid];
        #pragma unroll
        for (int j = 16; j; j >>= 1) {
            u64 q = __shfl_xor_sync(0xffffffffu, p, j);
            bool keep_max = ((tid & k) == 0) == ((tid & j) == 0);
            bool sw = keep_max ? (q > p) : (q < p);
            if (sw) p = q;
        }
        sm[tid] = p;
        __syncthreads();
    }
    return p;
}

// ------------- per-image cutoff = 200th largest class-max key ----------------
__global__ void __launch_bounds__(1024, 1) k_thresh() {
    __shared__ u64 a[1024];
    int b = blockIdx.x, tid = threadIdx.x;
    u64 p = 0;
    if (tid < NCLS) {
        u32 mb = g_clsmax[b * NCLS + tid];
        if (__uint_as_float(mb) > 0.01f)
            p = ((u64)mb << 32) | (u32)(~(u32)(tid * MC));
    }
    sort1024_desc(p, a, tid);
    if (tid == 0) g_tkey[b] = a[199];
}

// -------- collect all (class, anchor) with score bits >= cutoff-hi ------------
// warp per anchor; 5 independent float4 loads per lane (high MLP), then test.
__global__ void __launch_bounds__(256) k_collect(const float* __restrict__ in) {
    int b    = blockIdx.y;
    int a    = blockIdx.x * 8 + (threadIdx.x >> 5);
    int lane = threadIdx.x & 31;
    if (a >= NANCH) return;

    u32 th = (u32)(g_tkey[b] >> 32);
    if (th < 0x3C23D70Bu) th = 0x3C23D70Bu;    // never below "> 0.01f"
    float fth = __uint_as_float(th);

    const float4* row4 = (const float4*)(in + ((size_t)b * NANCH + a) * ROWD);

    float4 v[5];
    #pragma unroll
    for (int i = 0; i < 5; i++) {
        int idx = lane + 32 * i;                // 0..150 valid (151 float4 per row)
        v[i] = (idx < 151) ? __ldg(&row4[idx]) : make_float4(0.f, 0.f, 0.f, 0.f);
    }

    #pragma unroll
    for (int i = 0; i < 5; i++) {
        int base = 4 * (lane + 32 * i);
        #pragma unroll
        for (int s = 0; s < 4; s++) {
            float f = (s == 0) ? v[i].x : (s == 1) ? v[i].y : (s == 2) ? v[i].z : v[i].w;
            int j = base + s;                   // raw column; class c = j-1
            if (j >= 1 && j <= NCLS && f >= fth) {
                u32 c = (u32)(j - 1);
                u32 ub = __float_as_uint(f);
                u32 p = atomicAdd(&g_ccnt[b], 1u);
                if (p < CAPN)
                    g_col[b * CAPN + p] =
                        ((u64)c << 46) | ((u64)ub << 14) | (u64)(0x3FFFu - (u32)a);
            }
        }
    }
}

// ---- final: sort candidates, per-class ranks + greedy NMS, top-200, encode ----
__global__ void __launch_bounds__(1024, 1) k_nms_final(const float* __restrict__ in,
                                                       float* __restrict__ out) {
    __shared__ u64    skey[1024];
    __shared__ float4 sbox[1024];
    __shared__ float  sarea[1024];
    __shared__ u32    skept[1024];
    __shared__ u32    saux[1024];

    int b = blockIdx.x, tid = threadIdx.x;
    u32 n = min(g_ccnt[b], (u32)CAPN);

    // ---- phase A: sort collected keys desc (class desc, score desc, anchor asc) ----
    u64 p = ((u32)tid < n) ? g_col[b * CAPN + tid] : 0ull;
    sort1024_desc(p, skey, tid);

    bool valid = (u32)tid < n;
    u32 c = 0, ub = 0, anch = 0;
    if (valid) {
        u64 key = skey[tid];
        c    = (u32)(key >> 46);
        ub   = (u32)(key >> 14);
        anch = 0x3FFFu - (u32)(key & 0x3FFFu);
        const float4 bx = *(const float4*)(in + ((size_t)b * NANCH + anch) * ROWD + 600);
        // bx = (cx, cy, w, h) -> exact reference corner encode
        float y0 = __fsub_rn(bx.y, __fmul_rn(bx.w, 0.5f));
        float x0 = __fsub_rn(bx.x, __fmul_rn(bx.z, 0.5f));
        float y1 = __fadd_rn(bx.y, __fmul_rn(bx.w, 0.5f));
        float x1 = __fadd_rn(bx.x, __fmul_rn(bx.z, 0.5f));
        sbox[tid]  = make_float4(y0, x0, y1, x1);
        sarea[tid] = __fmul_rn(__fsub_rn(y1, y0), __fsub_rn(x1, x0));
        skept[tid] = 0;
    }

    // rank within class = distance to segment start (segments are tiny)
    int r = 0;
    if (valid)
        while (tid - r - 1 >= 0 && (u32)(skey[tid - r - 1] >> 46) == c) r++;
    __syncthreads();

    // ---- per-class exact greedy NMS, one leader thread per class segment ----
    if (valid && r == 0) {
        skept[tid] = 1;
        for (int k = tid + 1; k < (int)n && (u32)(skey[k] >> 46) == c; k++) {
            float4 bk = sbox[k];
            float  ak = sarea[k];
            bool sup = false;
            for (int j = tid; j < k; j++) {
                if (skept[j]) {
                    float4 bj = sbox[j];
                    float ih = fmaxf(__fsub_rn(fminf(bj.z, bk.z), fmaxf(bj.x, bk.x)), 0.f);
                    float iw = fmaxf(__fsub_rn(fminf(bj.w, bk.w), fmaxf(bj.y, bk.y)), 0.f);
                    float inter = __fmul_rn(ih, iw);
                    float uni   = __fsub_rn(__fadd_rn(sarea[j], ak), inter);
                    if (uni > 0.f && __fdiv_rn(inter, uni) > 0.45f) { sup = true; break; }
                }
            }
            skept[k] = sup ? 0u : 1u;
        }
    }
    __syncthreads();

    // ---- build final keys: kept, in class top-300, above exact u64 cutoff ----
    u64 tk = g_tkey[b];
    u64 fk = 0; u32 pa = 0;
    if (valid && skept[tid] && r < MC) {
        u32 flat = c * MC + (u32)r;
        u64 cand = ((u64)ub << 32) | (u32)(~flat);
        if (cand >= tk) { fk = cand; pa = anch; }
    }
    __syncthreads();   // done reading skey/sbox before reuse

    // ---- phase B: sort (fk, anchor) desc, hybrid bitonic with aux ----
    p = fk;
    #pragma unroll
    for (int k = 2; k <= 32; k <<= 1)
        #pragma unroll
        for (int j = k >> 1; j; j >>= 1) {
            u64 q  = __shfl_xor_sync(0xffffffffu, p, j);
            u32 qa = __shfl_xor_sync(0xffffffffu, pa, j);
            bool keep_max = ((tid & k) == 0) == ((tid & j) == 0);
            bool sw = keep_max ? (q > p) : (q < p);
            if (sw) { p = q; pa = qa; }
        }
    skey[tid] = p; saux[tid] = pa;
    __syncthreads();
    for (int k = 64; k <= 1024; k <<= 1) {
        for (int j = k >> 1; j >= 32; j >>= 1) {
            int x = tid ^ j;
            if (x > tid) {
                u64 u1 = skey[tid], u2 = skey[x];
                bool sw = ((tid & k) == 0) ? (u1 < u2) : (u1 > u2);
                if (sw) {
                    skey[tid] = u2; skey[x] = u1;
                    u32 t2 = saux[tid]; saux[tid] = saux[x]; saux[x] = t2;
                }
            }
            __syncthreads();
        }
        p = skey[tid]; pa = saux[tid];
        #pragma unroll
        for (int j = 16; j; j >>= 1) {
            u64 q  = __shfl_xor_sync(0xffffffffu, p, j);
            u32 qa = __shfl_xor_sync(0xffffffffu, pa, j);
            bool keep_max = ((tid & k) == 0) == ((tid & j) == 0);
            bool sw = keep_max ? (q > p) : (q < p);
            if (sw) { p = q; pa = qa; }
        }
        skey[tid] = p; saux[tid] = pa;
        __syncthreads();
    }

    // ---- emit top-200 with exact corner -> center inverse transform ----
    if (tid < 200) {
        u64 key = skey[tid];
        float cls = 0.f, score = 0.f, ocx = 0.f, ocy = 0.f, otw = 0.f, oth = 0.f;
        if (key) {
            score = __uint_as_float((u32)(key >> 32));
            u32 flat = ~(u32)key;
            cls = (float)(flat / MC + 1);
            u32 anchor = saux[tid];
            const float4 bx = *(const float4*)(in + ((size_t)b * NANCH + anchor) * ROWD + 600);
            float y0 = __fsub_rn(bx.y, __fmul_rn(bx.w, 0.5f));
            float x0 = __fsub_rn(bx.x, __fmul_rn(bx.z, 0.5f));
            float y1 = __fadd_rn(bx.y, __fmul_rn(bx.w, 0.5f));
            float x1 = __fadd_rn(bx.x, __fmul_rn(bx.z, 0.5f));
            otw = __fsub_rn(x1, x0);
            oth = __fsub_rn(y1, y0);
            ocx = __fadd_rn(x0, __fmul_rn(otw, 0.5f));
            ocy = __fadd_rn(y0, __fmul_rn(oth, 0.5f));
        }
        float* o = out + ((size_t)b * 200 + tid) * 6;
        o[0] = cls; o[1] = score; o[2] = ocx; o[3] = ocy; o[4] = otw; o[5] = oth;
    }
}

// ------------------------------------------------------------------------------
extern "C" void kernel_launch(void* const* d_in, const int* in_sizes, int n_in,
                              void* d_out, int out_size) {
    const float* in = (const float*)d_in[0];
    float* out = (float*)d_out;

    k_reset<<<2, 1024>>>();
    k_clsmax<<<dim3(273, 2), 256>>>(in);
    k_thresh<<<2, 1024>>>();
    k_collect<<<dim3((NANCH + 7) / 8, 2), 256>>>(in);
    k_nms_final<<<2, 1024>>>(in, out);
}

// round 11
// speedup vs baseline: 5.9937x; 1.1060x over previous
#include <cuda_runtime.h>

#define NANCH 8732
#define NCLS  599
#define MC    300
#define CAPN  1024
#define ROWD  604
#define TH_COLLECT 0.9999f

typedef unsigned int u32;
typedef unsigned long long u64;

// ------------------- static device scratch (no allocations) -------------------
__device__ u64 g_col[2 * CAPN];        // collected candidate sortkeys
__device__ u32 g_ccnt[2];              // per-image collected counters
__device__ u32 g_fastok[2];            // fast-path validity flag (set by nms_final)

// ------------------------------- reset ---------------------------------------
__global__ void k_reset() { if (threadIdx.x < 2) g_ccnt[threadIdx.x] = 0; }

// -------- speculative collect: all scores >= TH_COLLECT, 2 anchors/warp -------
__device__ __forceinline__ void col_append(int b, u32 c, float f, u32 a) {
    u32 p = atomicAdd(&g_ccnt[b], 1u);
    if (p < CAPN)
        g_col[b * CAPN + p] =
            ((u64)c << 46) | ((u64)__float_as_uint(f) << 14) | (u64)(0x3FFFu - a);
}

__global__ void __launch_bounds__(256) k_collect(const float* __restrict__ in) {
    int b    = blockIdx.y;
    int w    = threadIdx.x >> 5, lane = threadIdx.x & 31;
    int a0   = blockIdx.x * 16 + w * 2;
    bool ok0 = a0 < NANCH, ok1 = a0 + 1 < NANCH;

    const float4* r0 = (const float4*)(in + ((size_t)b * NANCH + a0) * ROWD);
    const float4* r1 = (const float4*)(in + ((size_t)b * NANCH + a0 + 1) * ROWD);

    float4 v[5], u[5];
    #pragma unroll
    for (int i = 0; i < 5; i++) {
        int idx = lane + 32 * i;                 // 0..150 valid (151 float4/row)
        bool inr = idx < 151;
        v[i] = (ok0 && inr) ? __ldg(&r0[idx]) : make_float4(0.f, 0.f, 0.f, 0.f);
        u[i] = (ok1 && inr) ? __ldg(&r1[idx]) : make_float4(0.f, 0.f, 0.f, 0.f);
    }

    #pragma unroll
    for (int i = 0; i < 5; i++) {
        int base = 4 * (lane + 32 * i);
        float fv[4] = {v[i].x, v[i].y, v[i].z, v[i].w};
        float fu[4] = {u[i].x, u[i].y, u[i].z, u[i].w};
        #pragma unroll
        for (int s = 0; s < 4; s++) {
            int j = base + s;                    // raw column; class = j-1
            if (j >= 1 && j <= NCLS) {
                if (fv[s] >= TH_COLLECT) col_append(b, (u32)(j - 1), fv[s], (u32)a0);
                if (fu[s] >= TH_COLLECT) col_append(b, (u32)(j - 1), fu[s], (u32)(a0 + 1));
            }
        }
    }
}

// ------------- hybrid bitonic 1024 desc (shfl j<=16, smem j>=32) --------------
__device__ __forceinline__ u64 sort1024_desc(u64 p, u64* sm, int tid) {
    #pragma unroll
    for (int k = 2; k <= 32; k <<= 1)
        #pragma unroll
        for (int j = k >> 1; j; j >>= 1) {
            u64 q = __shfl_xor_sync(0xffffffffu, p, j);
            bool keep_max = ((tid & k) == 0) == ((tid & j) == 0);
            bool sw = keep_max ? (q > p) : (q < p);
            if (sw) p = q;
        }
    sm[tid] = p;
    __syncthreads();
    for (int k = 64; k <= 1024; k <<= 1) {
        for (int j = k >> 1; j >= 32; j >>= 1) {
            int x = tid ^ j;
            if (x > tid) {
                u64 a = sm[tid], bb = sm[x];
                bool sw = ((tid & k) == 0) ? (a < bb) : (a > bb);
                if (sw) { sm[tid] = bb; sm[x] = a; }
            }
            __syncthreads();
        }
        p = sm[tid];
        #pragma unroll
        for (int j = 16; j; j >>= 1) {
            u64 q = __shfl_xor_sync(0xffffffffu, p, j);
            bool keep_max = ((tid & k) == 0) == ((tid & j) == 0);
            bool sw = keep_max ? (q > p) : (q < p);
            if (sw) p = q;
        }
        sm[tid] = p;
        __syncthreads();
    }
    return p;
}

// --------------------------- shared final-stage pieces ------------------------
struct Cand { bool valid; u32 c, ub, anch; int r; };

__device__ __forceinline__ Cand extract_rank(const float* __restrict__ in, int b, int tid,
        u32 n, u64* skey, u32* sclass, float4* sbox, float* sarea, u32* skept) {
    Cand cd; cd.valid = (u32)tid < n; cd.c = 0; cd.ub = 0; cd.anch = 0; cd.r = 0;
    skept[tid] = 0;
    if (cd.valid) {
        u64 key = skey[tid];
        cd.c    = (u32)(key >> 46);
        cd.ub   = (u32)(key >> 14);
        cd.anch = 0x3FFFu - (u32)(key & 0x3FFFu);
        sclass[tid] = cd.c;
        const float4 bx = *(const float4*)(in + ((size_t)b * NANCH + cd.anch) * ROWD + 600);
        // bx = (cx, cy, w, h) -> exact reference corner encode
        float y0 = __fsub_rn(bx.y, __fmul_rn(bx.w, 0.5f));
        float x0 = __fsub_rn(bx.x, __fmul_rn(bx.z, 0.5f));
        float y1 = __fadd_rn(bx.y, __fmul_rn(bx.w, 0.5f));
        float x1 = __fadd_rn(bx.x, __fmul_rn(bx.z, 0.5f));
        sbox[tid]  = make_float4(y0, x0, y1, x1);
        sarea[tid] = __fmul_rn(__fsub_rn(y1, y0), __fsub_rn(x1, x0));
        int r = 0;
        while (tid - r - 1 >= 0 && (u32)(skey[tid - r - 1] >> 46) == cd.c) r++;
        cd.r = r;
    }
    __syncthreads();
    return cd;
}

__device__ __forceinline__ void nms_mark(int tid, u32 n, const Cand& cd,
        u32* sclass, float4* sbox, float* sarea, u32* skept) {
    if (cd.valid && cd.r == 0) {                 // one leader per class segment
        skept[tid] = 1;
        for (int k = tid + 1; k < (int)n && sclass[k] == cd.c; k++) {
            float4 bk = sbox[k];
            float  ak = sarea[k];
            bool sup = false;
            for (int j = tid; j < k; j++) {
                if (skept[j]) {
                    float4 bj = sbox[j];
                    float ih = fmaxf(__fsub_rn(fminf(bj.z, bk.z), fmaxf(bj.x, bk.x)), 0.f);
                    float iw = fmaxf(__fsub_rn(fminf(bj.w, bk.w), fmaxf(bj.y, bk.y)), 0.f);
                    float inter = __fmul_rn(ih, iw);
                    float uni   = __fsub_rn(__fadd_rn(sarea[j], ak), inter);
                    if (uni > 0.f && __fdiv_rn(inter, uni) > 0.45f) { sup = true; break; }
                }
            }
            skept[k] = sup ? 0u : 1u;
        }
    }
    __syncthreads();
}

__device__ __forceinline__ void sort_emit(const float* __restrict__ in,
        float* __restrict__ out, int b, int tid, u64 p, u32 pa, u64* skey, u32* saux) {
    __syncthreads();                             // prior skey readers done
    #pragma unroll
    for (int k = 2; k <= 32; k <<= 1)
        #pragma unroll
        for (int j = k >> 1; j; j >>= 1) {
            u64 q  = __shfl_xor_sync(0xffffffffu, p, j);
            u32 qa = __shfl_xor_sync(0xffffffffu, pa, j);
            bool keep_max = ((tid & k) == 0) == ((tid & j) == 0);
            bool sw = keep_max ? (q > p) : (q < p);
            if (sw) { p = q; pa = qa; }
        }
    skey[tid] = p; saux[tid] = pa;
    __syncthreads();
    for (int k = 64; k <= 1024; k <<= 1) {
        for (int j = k >> 1; j >= 32; j >>= 1) {
            int x = tid ^ j;
            if (x > tid) {
                u64 u1 = skey[tid], u2 = skey[x];
                bool sw = ((tid & k) == 0) ? (u1 < u2) : (u1 > u2);
                if (sw) {
                    skey[tid] = u2; skey[x] = u1;
                    u32 t2 = saux[tid]; saux[tid] = saux[x]; saux[x] = t2;
                }
            }
            __syncthreads();
        }
        p = skey[tid]; pa = saux[tid];
        #pragma unroll
        for (int j = 16; j; j >>= 1) {
            u64 q  = __shfl_xor_sync(0xffffffffu, p, j);
            u32 qa = __shfl_xor_sync(0xffffffffu, pa, j);
            bool keep_max = ((tid & k) == 0) == ((tid & j) == 0);
            bool sw = keep_max ? (q > p) : (q < p);
            if (sw) { p = q; pa = qa; }
        }
        skey[tid] = p; saux[tid] = pa;
        __syncthreads();
    }

    if (tid < 200) {
        u64 key = skey[tid];
        float cls = 0.f, score = 0.f, ocx = 0.f, ocy = 0.f, otw = 0.f, oth = 0.f;
        if (key) {
            score = __uint_as_float((u32)(key >> 32));
            u32 flat = ~(u32)key;
            cls = (float)(flat / MC + 1);
            u32 anchor = saux[tid];
            const float4 bx = *(const float4*)(in + ((size_t)b * NANCH + anchor) * ROWD + 600);
            float y0 = __fsub_rn(bx.y, __fmul_rn(bx.w, 0.5f));
            float x0 = __fsub_rn(bx.x, __fmul_rn(bx.z, 0.5f));
            float y1 = __fadd_rn(bx.y, __fmul_rn(bx.w, 0.5f));
            float x1 = __fadd_rn(bx.x, __fmul_rn(bx.z, 0.5f));
            otw = __fsub_rn(x1, x0);
            oth = __fsub_rn(y1, y0);
            ocx = __fadd_rn(x0, __fmul_rn(otw, 0.5f));
            ocy = __fadd_rn(y0, __fmul_rn(oth, 0.5f));
        }
        float* o = out + ((size_t)b * 200 + tid) * 6;
        o[0] = cls; o[1] = score; o[2] = ocx; o[3] = ocy; o[4] = otw; o[5] = oth;
    }
}

// ---- fast path: sort, derive exact tkey from class heads, NMS, filter, emit ----
__global__ void __launch_bounds__(1024, 1) k_nms_final(const float* __restrict__ in,
                                                       float* __restrict__ out) {
    __shared__ u64    skey[1024];
    __shared__ u32    sclass[1024];
    __shared__ float4 sbox[1024];
    __shared__ float  sarea[1024];
    __shared__ u32    skept[1024];
    __shared__ u32    saux[1024];

    int b = blockIdx.x, tid = threadIdx.x;
    u32 raw = g_ccnt[b];
    u32 n = min(raw, (u32)CAPN);

    u64 p = ((u32)tid < n) ? g_col[b * CAPN + tid] : 0ull;
    sort1024_desc(p, skey, tid);                 // class desc, score desc, anchor asc

    Cand cd = extract_rank(in, b, tid, n, skey, sclass, sbox, sarea, skept);

    // distinct classes + exact tkey from class-segment heads
    int D = __syncthreads_count(cd.valid && cd.r == 0);
    u64 k2 = (cd.valid && cd.r == 0)
           ? (((u64)cd.ub << 32) | (u32)(~(u32)(cd.c * MC))) : 0ull;
    sort1024_desc(k2, skey, tid);                // clobbers skey (boxes/class kept)
    u64 tkey = skey[199];

    bool fastok = (D >= 200) && (raw <= (u32)CAPN);
    if (tid == 0) g_fastok[b] = fastok ? 1u : 0u;
    if (!fastok) return;                         // fallback kernel emits instead

    nms_mark(tid, n, cd, sclass, sbox, sarea, skept);

    u64 fk = 0; u32 pa = 0;
    if (cd.valid && skept[tid] && cd.r < MC) {
        u64 candk = ((u64)cd.ub << 32) | (u32)(~(u32)(cd.c * MC + (u32)cd.r));
        if (candk >= tkey) { fk = candk; pa = cd.anch; }
    }
    sort_emit(in, out, b, tid, fk, pa, skey, saux);
}

// ---- exact fallback (never taken for valid speculation; correctness anchor) ----
__global__ void __launch_bounds__(1024, 1) k_fallback(const float* __restrict__ in,
                                                      float* __restrict__ out) {
    __shared__ u64    skey[1024];
    __shared__ u32    sclass[1024];
    __shared__ float4 sbox[1024];
    __shared__ float  sarea[1024];
    __shared__ u32    skept[1024];
    __shared__ u32    saux[1024];
    __shared__ u32    scnt;

    int b = blockIdx.x, tid = threadIdx.x;
    if (g_fastok[b]) return;                     // uniform across block

    // exact per-class max (thread tid owns class tid)
    float m = 0.f;
    if (tid < NCLS) {
        #pragma unroll 1
        for (int a = 0; a < NANCH; a++)
            m = fmaxf(m, __ldg(&in[((size_t)b * NANCH + a) * ROWD + 1 + tid]));
    }
    u64 p = (tid < NCLS && m > 0.01f)
          ? (((u64)__float_as_uint(m) << 32) | (u32)(~(u32)(tid * MC))) : 0ull;
    sort1024_desc(p, skey, tid);
    u64 tkey = skey[199];
    u32 th = (u32)(tkey >> 32);
    __syncthreads();

    // exact collect into smem
    if (tid == 0) scnt = 0;
    __syncthreads();
    if (tid < NCLS) {
        #pragma unroll 1
        for (int a = 0; a < NANCH; a++) {
            float v = __ldg(&in[((size_t)b * NANCH + a) * ROWD + 1 + tid]);
            if (v > 0.01f && __float_as_uint(v) >= th) {
                u32 pos = atomicAdd(&scnt, 1u);
                if (pos < CAPN)
                    skey[pos] = ((u64)tid << 46) | ((u64)__float_as_uint(v) << 14)
                              | (u64)(0x3FFFu - (u32)a);
            }
        }
    }
    __syncthreads();
    u32 n = min(scnt, (u32)CAPN);
    u64 q = ((u32)tid < n) ? skey[tid] : 0ull;
    __syncthreads();
    sort1024_desc(q, skey, tid);

    Cand cd = extract_rank(in, b, tid, n, skey, sclass, sbox, sarea, skept);
    nms_mark(tid, n, cd, sclass, sbox, sarea, skept);

    u64 fk = 0; u32 pa = 0;
    if (cd.valid && skept[tid] && cd.r < MC) {
        u64 candk = ((u64)cd.ub << 32) | (u32)(~(u32)(cd.c * MC + (u32)cd.r));
        if (candk >= tkey) { fk = candk; pa = cd.anch; }
    }
    sort_emit(in, out, b, tid, fk, pa, skey, saux);
}

// ------------------------------------------------------------------------------
extern "C" void kernel_launch(void* const* d_in, const int* in_sizes, int n_in,
                              void* d_out, int out_size) {
    const float* in = (const float*)d_in[0];
    float* out = (float*)d_out;

    k_reset<<<1, 32>>>();
    k_collect<<<dim3((NANCH + 15) / 16, 2), 256>>>(in);
    k_nms_final<<<2, 1024>>>(in, out);
    k_fallback<<<2, 1024>>>(in, out);
}

// round 12
// speedup vs baseline: 6.1034x; 1.0183x over previous
#include <cuda_runtime.h>

#define NANCH 8732
#define NCLS  599
#define MC    300
#define CAPN  1024
#define ROWD  604
#define TH_COLLECT 0.9999f

typedef unsigned int u32;
typedef unsigned long long u64;

// ------------------- static device scratch (no allocations) -------------------
__device__ u64 g_col[2 * CAPN];        // collected candidate sortkeys
__device__ u32 g_ccnt[2];              // per-image collected counters (self-resetting)

// -------- speculative collect: all scores >= TH_COLLECT, 2 anchors/warp -------
__device__ __forceinline__ void col_append(int b, u32 c, float f, u32 a) {
    u32 p = atomicAdd(&g_ccnt[b], 1u);
    if (p < CAPN)
        g_col[b * CAPN + p] =
            ((u64)c << 46) | ((u64)__float_as_uint(f) << 14) | (u64)(0x3FFFu - a);
}

__global__ void __launch_bounds__(256) k_collect(const float* __restrict__ in) {
    int b    = blockIdx.y;
    int w    = threadIdx.x >> 5, lane = threadIdx.x & 31;
    int a0   = blockIdx.x * 16 + w * 2;
    bool ok0 = a0 < NANCH, ok1 = a0 + 1 < NANCH;

    const float4* r0 = (const float4*)(in + ((size_t)b * NANCH + a0) * ROWD);
    const float4* r1 = (const float4*)(in + ((size_t)b * NANCH + a0 + 1) * ROWD);

    float4 v[5], u[5];
    #pragma unroll
    for (int i = 0; i < 5; i++) {
        int idx = lane + 32 * i;                 // 0..150 valid (151 float4/row)
        bool inr = idx < 151;
        v[i] = (ok0 && inr) ? __ldg(&r0[idx]) : make_float4(0.f, 0.f, 0.f, 0.f);
        u[i] = (ok1 && inr) ? __ldg(&r1[idx]) : make_float4(0.f, 0.f, 0.f, 0.f);
    }

    #pragma unroll
    for (int i = 0; i < 5; i++) {
        int base = 4 * (lane + 32 * i);
        float fv[4] = {v[i].x, v[i].y, v[i].z, v[i].w};
        float fu[4] = {u[i].x, u[i].y, u[i].z, u[i].w};
        #pragma unroll
        for (int s = 0; s < 4; s++) {
            int j = base + s;                    // raw column; class = j-1
            if (j >= 1 && j <= NCLS) {
                if (fv[s] >= TH_COLLECT) col_append(b, (u32)(j - 1), fv[s], (u32)a0);
                if (fu[s] >= TH_COLLECT) col_append(b, (u32)(j - 1), fu[s], (u32)(a0 + 1));
            }
        }
    }
}

// ------------- hybrid bitonic 1024 desc (shfl j<=16, smem j>=32) --------------
__device__ __forceinline__ u64 sort1024_desc(u64 p, u64* sm, int tid) {
    #pragma unroll
    for (int k = 2; k <= 32; k <<= 1)
        #pragma unroll
        for (int j = k >> 1; j; j >>= 1) {
            u64 q = __shfl_xor_sync(0xffffffffu, p, j);
            bool keep_max = ((tid & k) == 0) == ((tid & j) == 0);
            bool sw = keep_max ? (q > p) : (q < p);
            if (sw) p = q;
        }
    sm[tid] = p;
    __syncthreads();
    for (int k = 64; k <= 1024; k <<= 1) {
        for (int j = k >> 1; j >= 32; j >>= 1) {
            int x = tid ^ j;
            if (x > tid) {
                u64 a = sm[tid], bb = sm[x];
                bool sw = ((tid & k) == 0) ? (a < bb) : (a > bb);
                if (sw) { sm[tid] = bb; sm[x] = a; }
            }
            __syncthreads();
        }
        p = sm[tid];
        #pragma unroll
        for (int j = 16; j; j >>= 1) {
            u64 q = __shfl_xor_sync(0xffffffffu, p, j);
            bool keep_max = ((tid & k) == 0) == ((tid & j) == 0);
            bool sw = keep_max ? (q > p) : (q < p);
            if (sw) p = q;
        }
        sm[tid] = p;
        __syncthreads();
    }
    return p;
}

// --------------------------- shared final-stage pieces ------------------------
struct Cand { bool valid; u32 c, ub, anch; int r; };

__device__ __forceinline__ Cand extract_rank(const float* __restrict__ in, int b, int tid,
        u32 n, u64* skey, u32* sclass, float4* sbox, float* sarea, u32* skept) {
    Cand cd; cd.valid = (u32)tid < n; cd.c = 0; cd.ub = 0; cd.anch = 0; cd.r = 0;
    skept[tid] = 0;
    if (cd.valid) {
        u64 key = skey[tid];
        cd.c    = (u32)(key >> 46);
        cd.ub   = (u32)(key >> 14);
        cd.anch = 0x3FFFu - (u32)(key & 0x3FFFu);
        sclass[tid] = cd.c;
        const float4 bx = *(const float4*)(in + ((size_t)b * NANCH + cd.anch) * ROWD + 600);
        // bx = (cx, cy, w, h) -> exact reference corner encode
        float y0 = __fsub_rn(bx.y, __fmul_rn(bx.w, 0.5f));
        float x0 = __fsub_rn(bx.x, __fmul_rn(bx.z, 0.5f));
        float y1 = __fadd_rn(bx.y, __fmul_rn(bx.w, 0.5f));
        float x1 = __fadd_rn(bx.x, __fmul_rn(bx.z, 0.5f));
        sbox[tid]  = make_float4(y0, x0, y1, x1);
        sarea[tid] = __fmul_rn(__fsub_rn(y1, y0), __fsub_rn(x1, x0));
        int r = 0;
        while (tid - r - 1 >= 0 && (u32)(skey[tid - r - 1] >> 46) == cd.c) r++;
        cd.r = r;
    }
    __syncthreads();
    return cd;
}

__device__ __forceinline__ void nms_mark(int tid, u32 n, const Cand& cd,
        u32* sclass, float4* sbox, float* sarea, u32* skept) {
    if (cd.valid && cd.r == 0) {                 // one leader per class segment
        skept[tid] = 1;
        for (int k = tid + 1; k < (int)n && sclass[k] == cd.c; k++) {
            float4 bk = sbox[k];
            float  ak = sarea[k];
            bool sup = false;
            for (int j = tid; j < k; j++) {
                if (skept[j]) {
                    float4 bj = sbox[j];
                    float ih = fmaxf(__fsub_rn(fminf(bj.z, bk.z), fmaxf(bj.x, bk.x)), 0.f);
                    float iw = fmaxf(__fsub_rn(fminf(bj.w, bk.w), fmaxf(bj.y, bk.y)), 0.f);
                    float inter = __fmul_rn(ih, iw);
                    float uni   = __fsub_rn(__fadd_rn(sarea[j], ak), inter);
                    if (uni > 0.f && __fdiv_rn(inter, uni) > 0.45f) { sup = true; break; }
                }
            }
            skept[k] = sup ? 0u : 1u;
        }
    }
    __syncthreads();
}

__device__ __forceinline__ void sort_emit(const float* __restrict__ in,
        float* __restrict__ out, int b, int tid, u64 p, u32 pa, u64* skey, u32* saux) {
    __syncthreads();                             // prior skey readers done
    #pragma unroll
    for (int k = 2; k <= 32; k <<= 1)
        #pragma unroll
        for (int j = k >> 1; j; j >>= 1) {
            u64 q  = __shfl_xor_sync(0xffffffffu, p, j);
            u32 qa = __shfl_xor_sync(0xffffffffu, pa, j);
            bool keep_max = ((tid & k) == 0) == ((tid & j) == 0);
            bool sw = keep_max ? (q > p) : (q < p);
            if (sw) { p = q; pa = qa; }
        }
    skey[tid] = p; saux[tid] = pa;
    __syncthreads();
    for (int k = 64; k <= 1024; k <<= 1) {
        for (int j = k >> 1; j >= 32; j >>= 1) {
            int x = tid ^ j;
            if (x > tid) {
                u64 u1 = skey[tid], u2 = skey[x];
                bool sw = ((tid & k) == 0) ? (u1 < u2) : (u1 > u2);
                if (sw) {
                    skey[tid] = u2; skey[x] = u1;
                    u32 t2 = saux[tid]; saux[tid] = saux[x]; saux[x] = t2;
                }
            }
            __syncthreads();
        }
        p = skey[tid]; pa = saux[tid];
        #pragma unroll
        for (int j = 16; j; j >>= 1) {
            u64 q  = __shfl_xor_sync(0xffffffffu, p, j);
            u32 qa = __shfl_xor_sync(0xffffffffu, pa, j);
            bool keep_max = ((tid & k) == 0) == ((tid & j) == 0);
            bool sw = keep_max ? (q > p) : (q < p);
            if (sw) { p = q; pa = qa; }
        }
        skey[tid] = p; saux[tid] = pa;
        __syncthreads();
    }

    if (tid < 200) {
        u64 key = skey[tid];
        float cls = 0.f, score = 0.f, ocx = 0.f, ocy = 0.f, otw = 0.f, oth = 0.f;
        if (key) {
            score = __uint_as_float((u32)(key >> 32));
            u32 flat = ~(u32)key;
            cls = (float)(flat / MC + 1);
            u32 anchor = saux[tid];
            const float4 bx = *(const float4*)(in + ((size_t)b * NANCH + anchor) * ROWD + 600);
            float y0 = __fsub_rn(bx.y, __fmul_rn(bx.w, 0.5f));
            float x0 = __fsub_rn(bx.x, __fmul_rn(bx.z, 0.5f));
            float y1 = __fadd_rn(bx.y, __fmul_rn(bx.w, 0.5f));
            float x1 = __fadd_rn(bx.x, __fmul_rn(bx.z, 0.5f));
            otw = __fsub_rn(x1, x0);
            oth = __fsub_rn(y1, y0);
            ocx = __fadd_rn(x0, __fmul_rn(otw, 0.5f));
            ocy = __fadd_rn(y0, __fmul_rn(oth, 0.5f));
        }
        float* o = out + ((size_t)b * 200 + tid) * 6;
        o[0] = cls; o[1] = score; o[2] = ocx; o[3] = ocy; o[4] = otw; o[5] = oth;
    }
}

// ---- final: fast path w/ derived exact tkey; inline exact fallback; self-reset ----
__global__ void __launch_bounds__(1024, 1) k_nms_final(const float* __restrict__ in,
                                                       float* __restrict__ out) {
    __shared__ u64    skey[1024];
    __shared__ u32    sclass[1024];
    __shared__ float4 sbox[1024];
    __shared__ float  sarea[1024];
    __shared__ u32    skept[1024];
    __shared__ u32    saux[1024];
    __shared__ u32    scnt;

    int b = blockIdx.x, tid = threadIdx.x;
    u32 raw = g_ccnt[b];
    u32 n = min(raw, (u32)CAPN);

    // ---- phase A: sort collected keys desc (class desc, score desc, anchor asc) ----
    u64 p = ((u32)tid < n) ? g_col[b * CAPN + tid] : 0ull;
    sort1024_desc(p, skey, tid);

    Cand cd = extract_rank(in, b, tid, n, skey, sclass, sbox, sarea, skept);

    // distinct classes + exact tkey from class-segment heads
    int D = __syncthreads_count(cd.valid && cd.r == 0);
    u64 k2 = (cd.valid && cd.r == 0)
           ? (((u64)cd.ub << 32) | (u32)(~(u32)(cd.c * MC))) : 0ull;
    sort1024_desc(k2, skey, tid);                // clobbers skey (boxes/class kept)
    u64 tkey = skey[199];

    bool fastok = (D >= 200) && (raw <= (u32)CAPN);   // block-uniform

    if (!fastok) {
        // ======== exact fallback (correctness anchor; never taken in practice) ====
        __syncthreads();
        float m = 0.f;
        if (tid < NCLS) {
            #pragma unroll 1
            for (int a = 0; a < NANCH; a++)
                m = fmaxf(m, __ldg(&in[((size_t)b * NANCH + a) * ROWD + 1 + tid]));
        }
        u64 pm = (tid < NCLS && m > 0.01f)
               ? (((u64)__float_as_uint(m) << 32) | (u32)(~(u32)(tid * MC))) : 0ull;
        sort1024_desc(pm, skey, tid);
        tkey = skey[199];
        u32 th = (u32)(tkey >> 32);
        __syncthreads();

        if (tid == 0) scnt = 0;
        __syncthreads();
        if (tid < NCLS) {
            #pragma unroll 1
            for (int a = 0; a < NANCH; a++) {
                float v = __ldg(&in[((size_t)b * NANCH + a) * ROWD + 1 + tid]);
                if (v > 0.01f && __float_as_uint(v) >= th) {
                    u32 pos = atomicAdd(&scnt, 1u);
                    if (pos < CAPN)
                        skey[pos] = ((u64)tid << 46) | ((u64)__float_as_uint(v) << 14)
                                  | (u64)(0x3FFFu - (u32)a);
                }
            }
        }
        __syncthreads();
        n = min(scnt, (u32)CAPN);
        u64 q = ((u32)tid < n) ? skey[tid] : 0ull;
        __syncthreads();
        sort1024_desc(q, skey, tid);
        cd = extract_rank(in, b, tid, n, skey, sclass, sbox, sarea, skept);
    }

    nms_mark(tid, n, cd, sclass, sbox, sarea, skept);

    u64 fk = 0; u32 pa = 0;
    if (cd.valid && skept[tid] && cd.r < MC) {
        u64 candk = ((u64)cd.ub << 32) | (u32)(~(u32)(cd.c * MC + (u32)cd.r));
        if (candk >= tkey) { fk = candk; pa = cd.anch; }
    }
    sort_emit(in, out, b, tid, fk, pa, skey, saux);

    // self-reset for the next graph replay (all g_col/g_ccnt reads are done)
    if (tid == 0) g_ccnt[b] = 0;
}

// ------------------------------------------------------------------------------
extern "C" void kernel_launch(void* const* d_in, const int* in_sizes, int n_in,
                              void* d_out, int out_size) {
    const float* in = (const float*)d_in[0];
    float* out = (float*)d_out;

    k_collect<<<dim3((NANCH + 15) / 16, 2), 256>>>(in);
    k_nms_final<<<2, 1024>>>(in, out);
}